// round 8
// baseline (speedup 1.0000x reference)
#include <cuda_runtime.h>
#include <math.h>

#define B_    128
#define PAST_ 256
#define FUT_  128
#define D_    128
#define RU_   512
#define LD_   128
#define FCN_  512
#define TL_   128
#define HDEC_ 640
#define G3RU  1536
#define G3HD  1920
#define MAXBLK 1024

// ---------------- static device scratch (no allocations anywhere) ----------
__device__ float g_gi_phi[(size_t)B_ * PAST_ * G3RU];   // 201 MB
__device__ float g_gi_xr [(size_t)B_ * FUT_  * G3RU];   // 100 MB
__device__ float g_h_phi [B_ * RU_];
__device__ float g_h_xr  [B_ * RU_];
__device__ float g_feat  [B_ * 2 * RU_];
__device__ float g_ghp   [2 * 4 * B_ * G3RU];           // enc gh partials [g][s][B][G3RU]
__device__ float g_m1p   [2 * 8 * B_ * 512];
__device__ float g_m2p   [2 * 4 * B_ * 256];
__device__ float g_m3p   [2 * 2 * B_ * 128];
__device__ float g_hdec  [B_ * HDEC_];
__device__ float g_xdec  [B_ * D_];
__device__ float g_dghp  [6 * B_ * G3HD];               // dec: s=0 Gi, s=1..5 Gh splits
__device__ float g_fcp   [5 * B_ * FCN_];
__device__ float g_outp  [4 * B_ * D_];
__device__ unsigned g_slots[MAXBLK];                    // barrier generation slots

// ---------------- lock-free grid barrier (per-block slots, no atomics) -----
// Slots are monotonic across graph replays; every block executes the same
// number of barriers, so at launch entry all slots hold the same generation.
__device__ __forceinline__ void gridbar(unsigned &gen) {
    gen++;
    __syncthreads();
    __threadfence();
    if (threadIdx.x == 0) *(volatile unsigned*)&g_slots[blockIdx.x] = gen;
    const int nb = gridDim.x;
    for (int s = threadIdx.x; s < nb; s += blockDim.x) {
        while (*(volatile unsigned*)&g_slots[s] < gen) { }
    }
    __threadfence();
    __syncthreads();
}

__device__ __forceinline__ float actf(float v, int act) {
    if (act == 1) return v > 0.f ? v : 0.01f * v;   // leaky_relu
    if (act == 2) return fmaxf(v, 0.f);             // relu
    return v;
}
__device__ __forceinline__ float sigm(float x) { return 1.f / (1.f + expf(-x)); }

__device__ __forceinline__ float4 ld4cg(const float* p) { return __ldcg((const float4*)p); }
__device__ __forceinline__ float4 ld4g (const float* p) { return __ldg ((const float4*)p); }
__device__ __forceinline__ void st4cg(float* p, float4 v) { __stcg((float4*)p, v); }

// ---------------- 32x64 tile GEMM, 256 threads, K-chunk = 128 --------------
// Register double-buffered: next chunk's A/W loads overlap current compute.
struct Smem {
    float As[32][36];
    float Ws[32][68];
};
struct Pref { float4 a, w0, w1; };

__device__ __forceinline__ Pref load_chunk(
    const float* __restrict__ A, int ldA, size_t partStride, int nred,
    const float* __restrict__ W, int ldW,
    int m0, int n0, int kb, int ar, int ac)
{
    Pref p;
    const float* ap = A + (size_t)(m0 + ar) * ldA + kb + ac;
    p.a = ld4cg(ap);
    for (int q = 1; q < nred; q++) {
        float4 u = ld4cg(ap + (size_t)q * partStride);
        p.a.x += u.x; p.a.y += u.y; p.a.z += u.z; p.a.w += u.w;
    }
    p.w0 = ld4g(W + (size_t)(n0 + ar) * ldW + kb + ac);
    p.w1 = ld4g(W + (size_t)(n0 + ar + 32) * ldW + kb + ac);
    return p;
}

__device__ __noinline__ void tile_gemm(
    Smem* sm,
    const float* __restrict__ A, int ldA, size_t partStride, int nred, int actIn,
    const float* __restrict__ W, int ldW,
    const float* __restrict__ bias, int addBias,
    float* __restrict__ C, int ldC,
    float* __restrict__ aux, int auxLd,
    int m0, int n0, int k0)
{
    const int tid = threadIdx.x;
    const int tx = tid & 15;        // 16 groups of 4 cols
    const int ty = tid >> 4;        // 16 groups of 2 rows
    const int ar = tid >> 3;        // 0..31 (A/W row)
    const int ac = (tid & 7) * 4;   // 0..28 (col)
    float acc[2][4];
#pragma unroll
    for (int i = 0; i < 2; i++)
#pragma unroll
        for (int j = 0; j < 4; j++) acc[i][j] = 0.f;

    Pref p = load_chunk(A, ldA, partStride, nred, W, ldW, m0, n0, k0, ar, ac);

#pragma unroll 1
    for (int kc = 0; kc < 4; kc++) {
        if (aux) st4cg(aux + (size_t)(m0 + ar) * auxLd + k0 + kc * 32 + ac, p.a);
        sm->As[ac + 0][ar] = actf(p.a.x, actIn);
        sm->As[ac + 1][ar] = actf(p.a.y, actIn);
        sm->As[ac + 2][ar] = actf(p.a.z, actIn);
        sm->As[ac + 3][ar] = actf(p.a.w, actIn);
        sm->Ws[ac + 0][ar] = p.w0.x;
        sm->Ws[ac + 1][ar] = p.w0.y;
        sm->Ws[ac + 2][ar] = p.w0.z;
        sm->Ws[ac + 3][ar] = p.w0.w;
        sm->Ws[ac + 0][ar + 32] = p.w1.x;
        sm->Ws[ac + 1][ar + 32] = p.w1.y;
        sm->Ws[ac + 2][ar + 32] = p.w1.z;
        sm->Ws[ac + 3][ar + 32] = p.w1.w;
        __syncthreads();
        if (kc < 3)
            p = load_chunk(A, ldA, partStride, nred, W, ldW, m0, n0, k0 + (kc + 1) * 32, ar, ac);
#pragma unroll
        for (int kk = 0; kk < 32; kk++) {
            float2 av = *(const float2*)&sm->As[kk][ty * 2];
            float4 wv = *(const float4*)&sm->Ws[kk][tx * 4];
            acc[0][0] = fmaf(av.x, wv.x, acc[0][0]);
            acc[0][1] = fmaf(av.x, wv.y, acc[0][1]);
            acc[0][2] = fmaf(av.x, wv.z, acc[0][2]);
            acc[0][3] = fmaf(av.x, wv.w, acc[0][3]);
            acc[1][0] = fmaf(av.y, wv.x, acc[1][0]);
            acc[1][1] = fmaf(av.y, wv.y, acc[1][1]);
            acc[1][2] = fmaf(av.y, wv.z, acc[1][2]);
            acc[1][3] = fmaf(av.y, wv.w, acc[1][3]);
        }
        __syncthreads();
    }

    const int n = n0 + tx * 4;
    float4 bv = addBias ? ld4g(bias + n) : make_float4(0.f, 0.f, 0.f, 0.f);
#pragma unroll
    for (int i = 0; i < 2; i++) {
        int m = m0 + ty * 2 + i;
        float4 v;
        v.x = acc[i][0] + bv.x;
        v.y = acc[i][1] + bv.y;
        v.z = acc[i][2] + bv.z;
        v.w = acc[i][3] + bv.w;
        st4cg(C + (size_t)m * ldC + n, v);
    }
}

// ---------------- persistent kernel ---------------------------------------
__global__ void __launch_bounds__(256) vae_persistent(
    const float* __restrict__ past, const float* __restrict__ future,
    const float* __restrict__ eps,
    const float* __restrict__ phi_Wih, const float* __restrict__ phi_Whh,
    const float* __restrict__ phi_bih, const float* __restrict__ phi_bhh,
    const float* __restrict__ xr_Wih,  const float* __restrict__ xr_Whh,
    const float* __restrict__ xr_bih,  const float* __restrict__ xr_bhh,
    const float* __restrict__ mu_W1, const float* __restrict__ mu_b1,
    const float* __restrict__ mu_W2, const float* __restrict__ mu_b2,
    const float* __restrict__ mu_W3, const float* __restrict__ mu_b3,
    const float* __restrict__ lv_W1, const float* __restrict__ lv_b1,
    const float* __restrict__ lv_W2, const float* __restrict__ lv_b2,
    const float* __restrict__ lv_W3, const float* __restrict__ lv_b3,
    const float* __restrict__ dec_Wih, const float* __restrict__ dec_Whh,
    const float* __restrict__ dec_bih, const float* __restrict__ dec_bhh,
    const float* __restrict__ fc_W, const float* __restrict__ fc_b,
    const float* __restrict__ out_W, const float* __restrict__ out_b,
    float* __restrict__ x_mu, float* __restrict__ z_mu_o, float* __restrict__ z_lv_o)
{
    __shared__ Smem sm;
    const int nblk = gridDim.x;
    const int bid  = blockIdx.x;
    const int tid  = threadIdx.x;
    const int gtid = bid * 256 + tid;
    const int nthr = nblk * 256;

    // barrier generation base (monotonic across replays; uniform at entry)
    unsigned gen = *(volatile unsigned*)&g_slots[bid];

    // ---------- P0: time-parallel input projections + zero hidden ----------
    {
        const int T1 = (B_ * PAST_ / 32) * (G3RU / 64);   // 24576
        const int T2 = (B_ * FUT_  / 32) * (G3RU / 64);   // 12288
#pragma unroll 1
        for (int tl = bid; tl < T1 + T2; tl += nblk) {
            if (tl < T1) {
                int m0 = (tl / 24) * 32, n0 = (tl % 24) * 64;
                tile_gemm(&sm, past, D_, 0, 1, 0, phi_Wih, D_, phi_bih, 1,
                          g_gi_phi, G3RU, 0, 0, m0, n0, 0);
            } else {
                int r = tl - T1;
                int m0 = (r / 24) * 32, n0 = (r % 24) * 64;
                tile_gemm(&sm, future, D_, 0, 1, 0, xr_Wih, D_, xr_bih, 1,
                          g_gi_xr, G3RU, 0, 0, m0, n0, 0);
            }
        }
        for (int i = gtid; i < 2 * B_ * RU_ / 4; i += nthr) {
            float4 z = make_float4(0.f, 0.f, 0.f, 0.f);
            if (i < B_ * RU_ / 4) st4cg(&g_h_phi[i * 4], z);
            else                  st4cg(&g_h_xr[(i - B_ * RU_ / 4) * 4], z);
        }
    }
    gridbar(gen);

    // ---------- encoder recurrences ----------
#pragma unroll 1
    for (int t = 0; t < PAST_; t++) {
        const int ngru = (t < FUT_) ? 2 : 1;
        const int TT = 4 * 24 * 4;   // m x n x ksplit = 384
#pragma unroll 1
        for (int tl = bid; tl < ngru * TT; tl += nblk) {
            int g = tl / TT, r = tl % TT;
            int s = r & 3; r >>= 2;
            int n0 = (r % 24) * 64, m0 = (r / 24) * 32;
            const float* A  = g ? g_h_xr : g_h_phi;
            const float* W  = g ? xr_Whh : phi_Whh;
            const float* bb = g ? xr_bhh : phi_bhh;
            float* C = g_ghp + ((size_t)g * 4 + s) * (B_ * G3RU);
            tile_gemm(&sm, A, RU_, 0, 1, 0, W, RU_, bb, s == 0, C, G3RU, 0, 0, m0, n0, s * 128);
        }
        gridbar(gen);
        // GRU pointwise, float4
        const int Q = RU_ / 4;   // 128
        for (int i = gtid; i < ngru * B_ * Q; i += nthr) {
            int g = i / (B_ * Q), r = i % (B_ * Q);
            int m = r / Q, j = (r % Q) * 4;
            float4 sr = make_float4(0.f,0.f,0.f,0.f), sz = sr, sn = sr;
#pragma unroll
            for (int s = 0; s < 4; s++) {
                const float* gp = g_ghp + ((size_t)g * 4 + s) * (B_ * G3RU) + (size_t)m * G3RU;
                float4 a = ld4cg(gp + j);
                float4 b = ld4cg(gp + RU_ + j);
                float4 c = ld4cg(gp + 2 * RU_ + j);
                sr.x+=a.x; sr.y+=a.y; sr.z+=a.z; sr.w+=a.w;
                sz.x+=b.x; sz.y+=b.y; sz.z+=b.z; sz.w+=b.w;
                sn.x+=c.x; sn.y+=c.y; sn.z+=c.z; sn.w+=c.w;
            }
            const float* gim = g ? (g_gi_xr  + ((size_t)m * FUT_  + t) * G3RU)
                                 : (g_gi_phi + ((size_t)m * PAST_ + t) * G3RU);
            float4 ir = ld4cg(gim + j), iz = ld4cg(gim + RU_ + j), in = ld4cg(gim + 2 * RU_ + j);
            float* hp = (g ? g_h_xr : g_h_phi) + (size_t)m * RU_ + j;
            float4 hv = ld4cg(hp);
            float4 o;
            {
                float rr = sigm(ir.x + sr.x), zz = sigm(iz.x + sz.x);
                float nn = tanhf(in.x + rr * sn.x);
                o.x = (1.f - zz) * nn + zz * hv.x;
            }
            {
                float rr = sigm(ir.y + sr.y), zz = sigm(iz.y + sz.y);
                float nn = tanhf(in.y + rr * sn.y);
                o.y = (1.f - zz) * nn + zz * hv.y;
            }
            {
                float rr = sigm(ir.z + sr.z), zz = sigm(iz.z + sz.z);
                float nn = tanhf(in.z + rr * sn.z);
                o.z = (1.f - zz) * nn + zz * hv.z;
            }
            {
                float rr = sigm(ir.w + sr.w), zz = sigm(iz.w + sz.w);
                float nn = tanhf(in.w + rr * sn.w);
                o.w = (1.f - zz) * nn + zz * hv.w;
            }
            st4cg(hp, o);
        }
        gridbar(gen);
    }

    // ---------- features ----------
    for (int i = gtid; i < B_ * 2 * RU_ / 4; i += nthr) {
        int m = i / (2 * RU_ / 4), c = (i % (2 * RU_ / 4)) * 4;
        float4 v = (c < RU_) ? ld4cg(&g_h_phi[m * RU_ + c]) : ld4cg(&g_h_xr[m * RU_ + c - RU_]);
        st4cg(&g_feat[m * 2 * RU_ + c], v);
    }
    gridbar(gen);

    // ---------- MLP L1: [B,512], K=1024 (S=8) ----------
#pragma unroll 1
    for (int tl = bid; tl < 2 * 4 * 8 * 8; tl += nblk) {
        int br = tl / 256, r = tl % 256;
        int s = r & 7; r >>= 3;
        int n0 = (r % 8) * 64, m0 = (r / 8) * 32;
        const float* W = br ? lv_W1 : mu_W1;
        const float* bb = br ? lv_b1 : mu_b1;
        float* C = g_m1p + ((size_t)br * 8 + s) * (B_ * 512);
        tile_gemm(&sm, g_feat, 2 * RU_, 0, 1, 0, W, 2 * RU_, bb, s == 0, C, 512, 0, 0, m0, n0, s * 128);
    }
    gridbar(gen);
    // ---------- MLP L2: [B,256], K=512 (S=4); A = leaky(sum8 L1) ----------
#pragma unroll 1
    for (int tl = bid; tl < 2 * 4 * 4 * 4; tl += nblk) {
        int br = tl / 64, r = tl % 64;
        int s = r & 3; r >>= 2;
        int n0 = (r % 4) * 64, m0 = (r / 4) * 32;
        const float* W = br ? lv_W2 : mu_W2;
        const float* bb = br ? lv_b2 : mu_b2;
        const float* A = g_m1p + (size_t)br * 8 * (B_ * 512);
        float* C = g_m2p + ((size_t)br * 4 + s) * (B_ * 256);
        tile_gemm(&sm, A, 512, (size_t)B_ * 512, 8, 1, W, 512, bb, s == 0, C, 256, 0, 0, m0, n0, s * 128);
    }
    gridbar(gen);
    // ---------- MLP L3: [B,128], K=256 (S=2); A = leaky(sum4 L2) ----------
#pragma unroll 1
    for (int tl = bid; tl < 2 * 4 * 2 * 2; tl += nblk) {
        int br = tl / 16, r = tl % 16;
        int s = r & 1; r >>= 1;
        int n0 = (r % 2) * 64, m0 = (r / 2) * 32;
        const float* W = br ? lv_W3 : mu_W3;
        const float* bb = br ? lv_b3 : mu_b3;
        const float* A = g_m2p + (size_t)br * 4 * (B_ * 256);
        float* C = g_m3p + ((size_t)br * 2 + s) * (B_ * 128);
        tile_gemm(&sm, A, 256, (size_t)B_ * 256, 4, 1, W, 256, bb, s == 0, C, 128, 0, 0, m0, n0, s * 128);
    }
    gridbar(gen);

    // ---------- prep decoder ----------
    for (int i = gtid; i < B_ * (HDEC_ + D_); i += nthr) {
        int m = i / (HDEC_ + D_), c = i % (HDEC_ + D_);
        if (c < RU_) {
            __stcg(&g_hdec[m * HDEC_ + c], __ldcg(&g_h_phi[m * RU_ + c]));
        } else if (c < HDEC_) {
            int l = c - RU_;
            float zm = __ldcg(&g_m3p[(size_t)0 * B_ * 128 + m * 128 + l])
                     + __ldcg(&g_m3p[(size_t)1 * B_ * 128 + m * 128 + l]);
            float zl = __ldcg(&g_m3p[(size_t)2 * B_ * 128 + m * 128 + l])
                     + __ldcg(&g_m3p[(size_t)3 * B_ * 128 + m * 128 + l]);
            z_mu_o[m * LD_ + l] = zm;
            z_lv_o[m * LD_ + l] = zl;
            float z = zm + __ldg(&eps[m * LD_ + l]) * expf(0.5f * zl);
            __stcg(&g_hdec[m * HDEC_ + c], z);
        } else {
            int d = c - HDEC_;
            __stcg(&g_xdec[m * D_ + d], __ldg(&past[((size_t)m * PAST_ + PAST_ - 1) * D_ + d]));
        }
    }
    gridbar(gen);

    // ---------- decoder recurrence (4 barriers / step) ----------
#pragma unroll 1
    for (int t = 0; t < TL_; t++) {
        // D1: gate partials. s=0: Gi (K=128; A = reduce of out partials, also
        // emits x_mu[:, t-1, :] from n0==0 tiles); s=1..5: Gh K-splits.
#pragma unroll 1
        for (int tl = bid; tl < 4 * 30 * 6; tl += nblk) {
            int s = tl % 6, r = tl / 6;
            int n0 = (r % 30) * 64, m0 = (r / 30) * 32;
            float* C = g_dghp + (size_t)s * (B_ * G3HD);
            if (s == 0) {
                if (t == 0) {
                    tile_gemm(&sm, g_xdec, D_, 0, 1, 0, dec_Wih, D_, dec_bih, 1,
                              C, G3HD, 0, 0, m0, n0, 0);
                } else {
                    float* aux = (n0 == 0) ? (x_mu + (size_t)(t - 1) * D_) : 0;
                    tile_gemm(&sm, g_outp, D_, (size_t)B_ * D_, 4, 0, dec_Wih, D_, dec_bih, 1,
                              C, G3HD, aux, TL_ * D_, m0, n0, 0);
                }
            } else {
                tile_gemm(&sm, g_hdec, HDEC_, 0, 1, 0, dec_Whh, HDEC_, dec_bhh, s == 1,
                          C, G3HD, 0, 0, m0, n0, (s - 1) * 128);
            }
        }
        gridbar(gen);
        // D2: GRU pointwise, float4
        const int Q = HDEC_ / 4;   // 160
        for (int i = gtid; i < B_ * Q; i += nthr) {
            int m = i / Q, j = (i % Q) * 4;
            const float* g0 = g_dghp + (size_t)m * G3HD;
            float4 ir = ld4cg(g0 + j), iz = ld4cg(g0 + HDEC_ + j), in = ld4cg(g0 + 2 * HDEC_ + j);
            float4 hr = make_float4(0.f,0.f,0.f,0.f), hz = hr, hn = hr;
#pragma unroll
            for (int s = 1; s < 6; s++) {
                const float* gp = g_dghp + (size_t)s * (B_ * G3HD) + (size_t)m * G3HD;
                float4 a = ld4cg(gp + j);
                float4 b = ld4cg(gp + HDEC_ + j);
                float4 c = ld4cg(gp + 2 * HDEC_ + j);
                hr.x+=a.x; hr.y+=a.y; hr.z+=a.z; hr.w+=a.w;
                hz.x+=b.x; hz.y+=b.y; hz.z+=b.z; hz.w+=b.w;
                hn.x+=c.x; hn.y+=c.y; hn.z+=c.z; hn.w+=c.w;
            }
            float* hp = &g_hdec[(size_t)m * HDEC_ + j];
            float4 hv = ld4cg(hp);
            float4 o;
            {
                float rr = sigm(ir.x + hr.x), zz = sigm(iz.x + hz.x);
                float nn = tanhf(in.x + rr * hn.x);
                o.x = (1.f - zz) * nn + zz * hv.x;
            }
            {
                float rr = sigm(ir.y + hr.y), zz = sigm(iz.y + hz.y);
                float nn = tanhf(in.y + rr * hn.y);
                o.y = (1.f - zz) * nn + zz * hv.y;
            }
            {
                float rr = sigm(ir.z + hr.z), zz = sigm(iz.z + hz.z);
                float nn = tanhf(in.z + rr * hn.z);
                o.z = (1.f - zz) * nn + zz * hv.z;
            }
            {
                float rr = sigm(ir.w + hr.w), zz = sigm(iz.w + hz.w);
                float nn = tanhf(in.w + rr * hn.w);
                o.w = (1.f - zz) * nn + zz * hv.w;
            }
            st4cg(hp, o);
        }
        gridbar(gen);
        // D3: fc partials [B,512], K=640 (S=5)
#pragma unroll 1
        for (int tl = bid; tl < 4 * 8 * 5; tl += nblk) {
            int s = tl % 5, r = tl / 5;
            int n0 = (r % 8) * 64, m0 = (r / 8) * 32;
            float* C = g_fcp + (size_t)s * (B_ * FCN_);
            tile_gemm(&sm, g_hdec, HDEC_, 0, 1, 0, fc_W, HDEC_, fc_b, s == 0, C, FCN_, 0, 0, m0, n0, s * 128);
        }
        gridbar(gen);
        // D4: out partials [B,128], K=512 (S=4); A = relu(sum5 fc)
#pragma unroll 1
        for (int tl = bid; tl < 4 * 2 * 4; tl += nblk) {
            int s = tl % 4, r = tl / 4;
            int n0 = (r % 2) * 64, m0 = (r / 2) * 32;
            float* C = g_outp + (size_t)s * (B_ * D_);
            tile_gemm(&sm, g_fcp, FCN_, (size_t)B_ * FCN_, 5, 2, out_W, FCN_, out_b, s == 0,
                      C, D_, 0, 0, m0, n0, s * 128);
        }
        gridbar(gen);
    }

    // ---------- final x_mu[:, TL-1, :] ----------
    for (int i = gtid; i < B_ * D_ / 4; i += nthr) {
        int m = i / 32, d = (i % 32) * 4;
        float4 v = make_float4(0.f,0.f,0.f,0.f);
#pragma unroll
        for (int s = 0; s < 4; s++) {
            float4 u = ld4cg(&g_outp[(size_t)s * B_ * D_ + m * D_ + d]);
            v.x+=u.x; v.y+=u.y; v.z+=u.z; v.w+=u.w;
        }
        *(float4*)&x_mu[((size_t)m * TL_ + TL_ - 1) * D_ + d] = v;
    }
}

// ---------------- host launch: single graph node ---------------------------
extern "C" void kernel_launch(void* const* d_in, const int* in_sizes, int n_in,
                              void* d_out, int out_size)
{
    (void)in_sizes; (void)n_in; (void)out_size;
    const float* past    = (const float*)d_in[0];
    const float* future  = (const float*)d_in[1];
    const float* eps     = (const float*)d_in[2];
    const float* phi_Wih = (const float*)d_in[3];
    const float* phi_Whh = (const float*)d_in[4];
    const float* phi_bih = (const float*)d_in[5];
    const float* phi_bhh = (const float*)d_in[6];
    const float* xr_Wih  = (const float*)d_in[7];
    const float* xr_Whh  = (const float*)d_in[8];
    const float* xr_bih  = (const float*)d_in[9];
    const float* xr_bhh  = (const float*)d_in[10];
    const float* mu_W1   = (const float*)d_in[11];
    const float* mu_b1   = (const float*)d_in[12];
    const float* mu_W2   = (const float*)d_in[13];
    const float* mu_b2   = (const float*)d_in[14];
    const float* mu_W3   = (const float*)d_in[15];
    const float* mu_b3   = (const float*)d_in[16];
    const float* lv_W1   = (const float*)d_in[17];
    const float* lv_b1   = (const float*)d_in[18];
    const float* lv_W2   = (const float*)d_in[19];
    const float* lv_b2   = (const float*)d_in[20];
    const float* lv_W3   = (const float*)d_in[21];
    const float* lv_b3   = (const float*)d_in[22];
    const float* dec_Wih = (const float*)d_in[23];
    const float* dec_Whh = (const float*)d_in[24];
    const float* dec_bih = (const float*)d_in[25];
    const float* dec_bhh = (const float*)d_in[26];
    const float* fc_W    = (const float*)d_in[27];
    const float* fc_b    = (const float*)d_in[28];
    const float* out_W   = (const float*)d_in[29];
    const float* out_b   = (const float*)d_in[30];

    float* outp = (float*)d_out;
    float* x_mu = outp;
    float* z_mu = outp + (size_t)B_ * TL_ * D_;
    float* z_lv = z_mu + (size_t)B_ * LD_;

    int dev = 0, sms = 148;
    cudaGetDevice(&dev);
    cudaDeviceGetAttribute(&sms, cudaDevAttrMultiProcessorCount, dev);
    int nblk = sms * 2;
    if (nblk > MAXBLK) nblk = MAXBLK;

    vae_persistent<<<nblk, 256>>>(
        past, future, eps,
        phi_Wih, phi_Whh, phi_bih, phi_bhh,
        xr_Wih, xr_Whh, xr_bih, xr_bhh,
        mu_W1, mu_b1, mu_W2, mu_b2, mu_W3, mu_b3,
        lv_W1, lv_b1, lv_W2, lv_b2, lv_W3, lv_b3,
        dec_Wih, dec_Whh, dec_bih, dec_bhh,
        fc_W, fc_b, out_W, out_b,
        x_mu, z_mu, z_lv);
}

// round 9
// speedup vs baseline: 1.1098x; 1.1098x over previous
#include <cuda_runtime.h>
#include <math.h>

#define B_    128
#define PAST_ 256
#define FUT_  128
#define D_    128
#define RU_   512
#define LD_   128
#define FCN_  512
#define TL_   128
#define HDEC_ 640
#define G3RU  1536
#define G3HD  1920
#define MAXBLK 1024

// ---------------- static device scratch (no allocations anywhere) ----------
__device__ float g_gi_phi[(size_t)B_ * PAST_ * G3RU];   // 201 MB
__device__ float g_gi_xr [(size_t)B_ * FUT_  * G3RU];   // 100 MB
__device__ float g_h_phi [B_ * RU_];
__device__ float g_h_xr  [B_ * RU_];
__device__ float g_feat  [B_ * 2 * RU_];
__device__ float g_ghp   [2 * 4 * B_ * G3RU];           // enc gh partials [g][s][B][G3RU]
__device__ float g_m1p   [2 * 8 * B_ * 512];
__device__ float g_m2p   [2 * 4 * B_ * 256];
__device__ float g_m3p   [2 * 2 * B_ * 128];
__device__ float g_hdec  [B_ * HDEC_];
__device__ float g_xdec  [B_ * D_];
__device__ float g_dghp  [6 * B_ * G3HD];               // dec: s=0 Gi, s=1..5 Gh splits
__device__ float g_fcp   [5 * B_ * FCN_];
__device__ float g_outp  [4 * B_ * D_];
__device__ unsigned g_slots[MAXBLK];                    // barrier generation slots

// ---------------- polite lock-free grid barrier ----------------------------
// Slots are monotonic across graph replays; every block executes the same
// number of barriers, so at launch entry all slots hold the same generation.
// Only warp 0 polls (strided over slots), with nanosleep backoff so waiting
// blocks do not steal LSU/issue bandwidth from still-computing blocks.
__device__ __forceinline__ void gridbar(unsigned &gen) {
    gen++;
    __syncthreads();
    __threadfence();
    if (threadIdx.x == 0) *(volatile unsigned*)&g_slots[blockIdx.x] = gen;
    if (threadIdx.x < 32) {
        const int nb = gridDim.x;
        unsigned delay = 64;
        for (;;) {
            bool done = true;
            for (int s = threadIdx.x; s < nb; s += 32)
                if (*(volatile unsigned*)&g_slots[s] < gen) done = false;
            if (__all_sync(0xffffffffu, done)) break;
            __nanosleep(delay);
            if (delay < 2048) delay <<= 1;
        }
        __threadfence();
    }
    __syncthreads();
}

__device__ __forceinline__ float actf(float v, int act) {
    if (act == 1) return v > 0.f ? v : 0.01f * v;   // leaky_relu
    if (act == 2) return fmaxf(v, 0.f);             // relu
    return v;
}
__device__ __forceinline__ float sigm(float x) { return 1.f / (1.f + expf(-x)); }

__device__ __forceinline__ float4 ld4cg(const float* p) { return __ldcg((const float4*)p); }
__device__ __forceinline__ float4 ld4g (const float* p) { return __ldg ((const float4*)p); }
__device__ __forceinline__ void st4cg(float* p, float4 v) { __stcg((float4*)p, v); }

// ---------------- 32x64 tile GEMM, 256 threads, K-chunk = 128 --------------
// Register double-buffered: next chunk's A/W loads overlap current compute.
struct Smem {
    float As[32][36];
    float Ws[32][68];
};
struct Pref { float4 a, w0, w1; };

__device__ __forceinline__ Pref load_chunk(
    const float* __restrict__ A, int ldA, size_t partStride, int nred,
    const float* __restrict__ W, int ldW,
    int m0, int n0, int kb, int ar, int ac)
{
    Pref p;
    const float* ap = A + (size_t)(m0 + ar) * ldA + kb + ac;
    p.a = ld4cg(ap);
    for (int q = 1; q < nred; q++) {
        float4 u = ld4cg(ap + (size_t)q * partStride);
        p.a.x += u.x; p.a.y += u.y; p.a.z += u.z; p.a.w += u.w;
    }
    p.w0 = ld4g(W + (size_t)(n0 + ar) * ldW + kb + ac);
    p.w1 = ld4g(W + (size_t)(n0 + ar + 32) * ldW + kb + ac);
    return p;
}

__device__ __noinline__ void tile_gemm(
    Smem* sm,
    const float* __restrict__ A, int ldA, size_t partStride, int nred, int actIn,
    const float* __restrict__ W, int ldW,
    const float* __restrict__ bias, int addBias,
    float* __restrict__ C, int ldC,
    float* __restrict__ aux, int auxLd,
    int m0, int n0, int k0)
{
    const int tid = threadIdx.x;
    const int tx = tid & 15;        // 16 groups of 4 cols
    const int ty = tid >> 4;        // 16 groups of 2 rows
    const int ar = tid >> 3;        // 0..31 (A/W row)
    const int ac = (tid & 7) * 4;   // 0..28 (col)
    float acc[2][4];
#pragma unroll
    for (int i = 0; i < 2; i++)
#pragma unroll
        for (int j = 0; j < 4; j++) acc[i][j] = 0.f;

    Pref p = load_chunk(A, ldA, partStride, nred, W, ldW, m0, n0, k0, ar, ac);

#pragma unroll 1
    for (int kc = 0; kc < 4; kc++) {
        if (aux) st4cg(aux + (size_t)(m0 + ar) * auxLd + k0 + kc * 32 + ac, p.a);
        sm->As[ac + 0][ar] = actf(p.a.x, actIn);
        sm->As[ac + 1][ar] = actf(p.a.y, actIn);
        sm->As[ac + 2][ar] = actf(p.a.z, actIn);
        sm->As[ac + 3][ar] = actf(p.a.w, actIn);
        sm->Ws[ac + 0][ar] = p.w0.x;
        sm->Ws[ac + 1][ar] = p.w0.y;
        sm->Ws[ac + 2][ar] = p.w0.z;
        sm->Ws[ac + 3][ar] = p.w0.w;
        sm->Ws[ac + 0][ar + 32] = p.w1.x;
        sm->Ws[ac + 1][ar + 32] = p.w1.y;
        sm->Ws[ac + 2][ar + 32] = p.w1.z;
        sm->Ws[ac + 3][ar + 32] = p.w1.w;
        __syncthreads();
        if (kc < 3)
            p = load_chunk(A, ldA, partStride, nred, W, ldW, m0, n0, k0 + (kc + 1) * 32, ar, ac);
#pragma unroll
        for (int kk = 0; kk < 32; kk++) {
            float2 av = *(const float2*)&sm->As[kk][ty * 2];
            float4 wv = *(const float4*)&sm->Ws[kk][tx * 4];
            acc[0][0] = fmaf(av.x, wv.x, acc[0][0]);
            acc[0][1] = fmaf(av.x, wv.y, acc[0][1]);
            acc[0][2] = fmaf(av.x, wv.z, acc[0][2]);
            acc[0][3] = fmaf(av.x, wv.w, acc[0][3]);
            acc[1][0] = fmaf(av.y, wv.x, acc[1][0]);
            acc[1][1] = fmaf(av.y, wv.y, acc[1][1]);
            acc[1][2] = fmaf(av.y, wv.z, acc[1][2]);
            acc[1][3] = fmaf(av.y, wv.w, acc[1][3]);
        }
        __syncthreads();
    }

    const int n = n0 + tx * 4;
    float4 bv = addBias ? ld4g(bias + n) : make_float4(0.f, 0.f, 0.f, 0.f);
#pragma unroll
    for (int i = 0; i < 2; i++) {
        int m = m0 + ty * 2 + i;
        float4 v;
        v.x = acc[i][0] + bv.x;
        v.y = acc[i][1] + bv.y;
        v.z = acc[i][2] + bv.z;
        v.w = acc[i][3] + bv.w;
        st4cg(C + (size_t)m * ldC + n, v);
    }
}

// ---------------- persistent kernel ---------------------------------------
__global__ void __launch_bounds__(256) vae_persistent(
    const float* __restrict__ past, const float* __restrict__ future,
    const float* __restrict__ eps,
    const float* __restrict__ phi_Wih, const float* __restrict__ phi_Whh,
    const float* __restrict__ phi_bih, const float* __restrict__ phi_bhh,
    const float* __restrict__ xr_Wih,  const float* __restrict__ xr_Whh,
    const float* __restrict__ xr_bih,  const float* __restrict__ xr_bhh,
    const float* __restrict__ mu_W1, const float* __restrict__ mu_b1,
    const float* __restrict__ mu_W2, const float* __restrict__ mu_b2,
    const float* __restrict__ mu_W3, const float* __restrict__ mu_b3,
    const float* __restrict__ lv_W1, const float* __restrict__ lv_b1,
    const float* __restrict__ lv_W2, const float* __restrict__ lv_b2,
    const float* __restrict__ lv_W3, const float* __restrict__ lv_b3,
    const float* __restrict__ dec_Wih, const float* __restrict__ dec_Whh,
    const float* __restrict__ dec_bih, const float* __restrict__ dec_bhh,
    const float* __restrict__ fc_W, const float* __restrict__ fc_b,
    const float* __restrict__ out_W, const float* __restrict__ out_b,
    float* __restrict__ x_mu, float* __restrict__ z_mu_o, float* __restrict__ z_lv_o)
{
    __shared__ Smem sm;
    const int nblk = gridDim.x;
    const int bid  = blockIdx.x;
    const int tid  = threadIdx.x;
    const int gtid = bid * 256 + tid;
    const int nthr = nblk * 256;

    // barrier generation base (monotonic across replays; uniform at entry)
    unsigned gen = *(volatile unsigned*)&g_slots[bid];

    // ---------- P0: time-parallel input projections + zero hidden ----------
    {
        const int T1 = (B_ * PAST_ / 32) * (G3RU / 64);   // 24576
        const int T2 = (B_ * FUT_  / 32) * (G3RU / 64);   // 12288
#pragma unroll 1
        for (int tl = bid; tl < T1 + T2; tl += nblk) {
            if (tl < T1) {
                int m0 = (tl / 24) * 32, n0 = (tl % 24) * 64;
                tile_gemm(&sm, past, D_, 0, 1, 0, phi_Wih, D_, phi_bih, 1,
                          g_gi_phi, G3RU, 0, 0, m0, n0, 0);
            } else {
                int r = tl - T1;
                int m0 = (r / 24) * 32, n0 = (r % 24) * 64;
                tile_gemm(&sm, future, D_, 0, 1, 0, xr_Wih, D_, xr_bih, 1,
                          g_gi_xr, G3RU, 0, 0, m0, n0, 0);
            }
        }
        for (int i = gtid; i < 2 * B_ * RU_ / 4; i += nthr) {
            float4 z = make_float4(0.f, 0.f, 0.f, 0.f);
            if (i < B_ * RU_ / 4) st4cg(&g_h_phi[i * 4], z);
            else                  st4cg(&g_h_xr[(i - B_ * RU_ / 4) * 4], z);
        }
    }
    gridbar(gen);

    // ---------- encoder recurrences ----------
#pragma unroll 1
    for (int t = 0; t < PAST_; t++) {
        const int ngru = (t < FUT_) ? 2 : 1;
        const int TT = 4 * 24 * 4;   // m x n x ksplit = 384
#pragma unroll 1
        for (int tl = bid; tl < ngru * TT; tl += nblk) {
            int g = tl / TT, r = tl % TT;
            int s = r & 3; r >>= 2;
            int n0 = (r % 24) * 64, m0 = (r / 24) * 32;
            const float* A  = g ? g_h_xr : g_h_phi;
            const float* W  = g ? xr_Whh : phi_Whh;
            const float* bb = g ? xr_bhh : phi_bhh;
            float* C = g_ghp + ((size_t)g * 4 + s) * (B_ * G3RU);
            tile_gemm(&sm, A, RU_, 0, 1, 0, W, RU_, bb, s == 0, C, G3RU, 0, 0, m0, n0, s * 128);
        }
        gridbar(gen);
        // GRU pointwise, float4
        const int Q = RU_ / 4;   // 128
        for (int i = gtid; i < ngru * B_ * Q; i += nthr) {
            int g = i / (B_ * Q), r = i % (B_ * Q);
            int m = r / Q, j = (r % Q) * 4;
            float4 sr = make_float4(0.f,0.f,0.f,0.f), sz = sr, sn = sr;
#pragma unroll
            for (int s = 0; s < 4; s++) {
                const float* gp = g_ghp + ((size_t)g * 4 + s) * (B_ * G3RU) + (size_t)m * G3RU;
                float4 a = ld4cg(gp + j);
                float4 b = ld4cg(gp + RU_ + j);
                float4 c = ld4cg(gp + 2 * RU_ + j);
                sr.x+=a.x; sr.y+=a.y; sr.z+=a.z; sr.w+=a.w;
                sz.x+=b.x; sz.y+=b.y; sz.z+=b.z; sz.w+=b.w;
                sn.x+=c.x; sn.y+=c.y; sn.z+=c.z; sn.w+=c.w;
            }
            const float* gim = g ? (g_gi_xr  + ((size_t)m * FUT_  + t) * G3RU)
                                 : (g_gi_phi + ((size_t)m * PAST_ + t) * G3RU);
            float4 ir = ld4cg(gim + j), iz = ld4cg(gim + RU_ + j), in = ld4cg(gim + 2 * RU_ + j);
            float* hp = (g ? g_h_xr : g_h_phi) + (size_t)m * RU_ + j;
            float4 hv = ld4cg(hp);
            float4 o;
            {
                float rr = sigm(ir.x + sr.x), zz = sigm(iz.x + sz.x);
                float nn = tanhf(in.x + rr * sn.x);
                o.x = (1.f - zz) * nn + zz * hv.x;
            }
            {
                float rr = sigm(ir.y + sr.y), zz = sigm(iz.y + sz.y);
                float nn = tanhf(in.y + rr * sn.y);
                o.y = (1.f - zz) * nn + zz * hv.y;
            }
            {
                float rr = sigm(ir.z + sr.z), zz = sigm(iz.z + sz.z);
                float nn = tanhf(in.z + rr * sn.z);
                o.z = (1.f - zz) * nn + zz * hv.z;
            }
            {
                float rr = sigm(ir.w + sr.w), zz = sigm(iz.w + sz.w);
                float nn = tanhf(in.w + rr * sn.w);
                o.w = (1.f - zz) * nn + zz * hv.w;
            }
            st4cg(hp, o);
        }
        gridbar(gen);
    }

    // ---------- features ----------
    for (int i = gtid; i < B_ * 2 * RU_ / 4; i += nthr) {
        int m = i / (2 * RU_ / 4), c = (i % (2 * RU_ / 4)) * 4;
        float4 v = (c < RU_) ? ld4cg(&g_h_phi[m * RU_ + c]) : ld4cg(&g_h_xr[m * RU_ + c - RU_]);
        st4cg(&g_feat[m * 2 * RU_ + c], v);
    }
    gridbar(gen);

    // ---------- MLP L1: [B,512], K=1024 (S=8) ----------
#pragma unroll 1
    for (int tl = bid; tl < 2 * 4 * 8 * 8; tl += nblk) {
        int br = tl / 256, r = tl % 256;
        int s = r & 7; r >>= 3;
        int n0 = (r % 8) * 64, m0 = (r / 8) * 32;
        const float* W = br ? lv_W1 : mu_W1;
        const float* bb = br ? lv_b1 : mu_b1;
        float* C = g_m1p + ((size_t)br * 8 + s) * (B_ * 512);
        tile_gemm(&sm, g_feat, 2 * RU_, 0, 1, 0, W, 2 * RU_, bb, s == 0, C, 512, 0, 0, m0, n0, s * 128);
    }
    gridbar(gen);
    // ---------- MLP L2: [B,256], K=512 (S=4); A = leaky(sum8 L1) ----------
#pragma unroll 1
    for (int tl = bid; tl < 2 * 4 * 4 * 4; tl += nblk) {
        int br = tl / 64, r = tl % 64;
        int s = r & 3; r >>= 2;
        int n0 = (r % 4) * 64, m0 = (r / 4) * 32;
        const float* W = br ? lv_W2 : mu_W2;
        const float* bb = br ? lv_b2 : mu_b2;
        const float* A = g_m1p + (size_t)br * 8 * (B_ * 512);
        float* C = g_m2p + ((size_t)br * 4 + s) * (B_ * 256);
        tile_gemm(&sm, A, 512, (size_t)B_ * 512, 8, 1, W, 512, bb, s == 0, C, 256, 0, 0, m0, n0, s * 128);
    }
    gridbar(gen);
    // ---------- MLP L3: [B,128], K=256 (S=2); A = leaky(sum4 L2) ----------
#pragma unroll 1
    for (int tl = bid; tl < 2 * 4 * 2 * 2; tl += nblk) {
        int br = tl / 16, r = tl % 16;
        int s = r & 1; r >>= 1;
        int n0 = (r % 2) * 64, m0 = (r / 2) * 32;
        const float* W = br ? lv_W3 : mu_W3;
        const float* bb = br ? lv_b3 : mu_b3;
        const float* A = g_m2p + (size_t)br * 4 * (B_ * 256);
        float* C = g_m3p + ((size_t)br * 2 + s) * (B_ * 128);
        tile_gemm(&sm, A, 256, (size_t)B_ * 256, 4, 1, W, 256, bb, s == 0, C, 128, 0, 0, m0, n0, s * 128);
    }
    gridbar(gen);

    // ---------- prep decoder ----------
    for (int i = gtid; i < B_ * (HDEC_ + D_); i += nthr) {
        int m = i / (HDEC_ + D_), c = i % (HDEC_ + D_);
        if (c < RU_) {
            __stcg(&g_hdec[m * HDEC_ + c], __ldcg(&g_h_phi[m * RU_ + c]));
        } else if (c < HDEC_) {
            int l = c - RU_;
            float zm = __ldcg(&g_m3p[(size_t)0 * B_ * 128 + m * 128 + l])
                     + __ldcg(&g_m3p[(size_t)1 * B_ * 128 + m * 128 + l]);
            float zl = __ldcg(&g_m3p[(size_t)2 * B_ * 128 + m * 128 + l])
                     + __ldcg(&g_m3p[(size_t)3 * B_ * 128 + m * 128 + l]);
            z_mu_o[m * LD_ + l] = zm;
            z_lv_o[m * LD_ + l] = zl;
            float z = zm + __ldg(&eps[m * LD_ + l]) * expf(0.5f * zl);
            __stcg(&g_hdec[m * HDEC_ + c], z);
        } else {
            int d = c - HDEC_;
            __stcg(&g_xdec[m * D_ + d], __ldg(&past[((size_t)m * PAST_ + PAST_ - 1) * D_ + d]));
        }
    }
    gridbar(gen);

    // ---------- decoder recurrence (4 barriers / step) ----------
#pragma unroll 1
    for (int t = 0; t < TL_; t++) {
        // D1: gate partials. s=0: Gi (K=128; A = reduce of out partials, also
        // emits x_mu[:, t-1, :] from n0==0 tiles); s=1..5: Gh K-splits.
#pragma unroll 1
        for (int tl = bid; tl < 4 * 30 * 6; tl += nblk) {
            int s = tl % 6, r = tl / 6;
            int n0 = (r % 30) * 64, m0 = (r / 30) * 32;
            float* C = g_dghp + (size_t)s * (B_ * G3HD);
            if (s == 0) {
                if (t == 0) {
                    tile_gemm(&sm, g_xdec, D_, 0, 1, 0, dec_Wih, D_, dec_bih, 1,
                              C, G3HD, 0, 0, m0, n0, 0);
                } else {
                    float* aux = (n0 == 0) ? (x_mu + (size_t)(t - 1) * D_) : 0;
                    tile_gemm(&sm, g_outp, D_, (size_t)B_ * D_, 4, 0, dec_Wih, D_, dec_bih, 1,
                              C, G3HD, aux, TL_ * D_, m0, n0, 0);
                }
            } else {
                tile_gemm(&sm, g_hdec, HDEC_, 0, 1, 0, dec_Whh, HDEC_, dec_bhh, s == 1,
                          C, G3HD, 0, 0, m0, n0, (s - 1) * 128);
            }
        }
        gridbar(gen);
        // D2: GRU pointwise, float4
        const int Q = HDEC_ / 4;   // 160
        for (int i = gtid; i < B_ * Q; i += nthr) {
            int m = i / Q, j = (i % Q) * 4;
            const float* g0 = g_dghp + (size_t)m * G3HD;
            float4 ir = ld4cg(g0 + j), iz = ld4cg(g0 + HDEC_ + j), in = ld4cg(g0 + 2 * HDEC_ + j);
            float4 hr = make_float4(0.f,0.f,0.f,0.f), hz = hr, hn = hr;
#pragma unroll
            for (int s = 1; s < 6; s++) {
                const float* gp = g_dghp + (size_t)s * (B_ * G3HD) + (size_t)m * G3HD;
                float4 a = ld4cg(gp + j);
                float4 b = ld4cg(gp + HDEC_ + j);
                float4 c = ld4cg(gp + 2 * HDEC_ + j);
                hr.x+=a.x; hr.y+=a.y; hr.z+=a.z; hr.w+=a.w;
                hz.x+=b.x; hz.y+=b.y; hz.z+=b.z; hz.w+=b.w;
                hn.x+=c.x; hn.y+=c.y; hn.z+=c.z; hn.w+=c.w;
            }
            float* hp = &g_hdec[(size_t)m * HDEC_ + j];
            float4 hv = ld4cg(hp);
            float4 o;
            {
                float rr = sigm(ir.x + hr.x), zz = sigm(iz.x + hz.x);
                float nn = tanhf(in.x + rr * hn.x);
                o.x = (1.f - zz) * nn + zz * hv.x;
            }
            {
                float rr = sigm(ir.y + hr.y), zz = sigm(iz.y + hz.y);
                float nn = tanhf(in.y + rr * hn.y);
                o.y = (1.f - zz) * nn + zz * hv.y;
            }
            {
                float rr = sigm(ir.z + hr.z), zz = sigm(iz.z + hz.z);
                float nn = tanhf(in.z + rr * hn.z);
                o.z = (1.f - zz) * nn + zz * hv.z;
            }
            {
                float rr = sigm(ir.w + hr.w), zz = sigm(iz.w + hz.w);
                float nn = tanhf(in.w + rr * hn.w);
                o.w = (1.f - zz) * nn + zz * hv.w;
            }
            st4cg(hp, o);
        }
        gridbar(gen);
        // D3: fc partials [B,512], K=640 (S=5)
#pragma unroll 1
        for (int tl = bid; tl < 4 * 8 * 5; tl += nblk) {
            int s = tl % 5, r = tl / 5;
            int n0 = (r % 8) * 64, m0 = (r / 8) * 32;
            float* C = g_fcp + (size_t)s * (B_ * FCN_);
            tile_gemm(&sm, g_hdec, HDEC_, 0, 1, 0, fc_W, HDEC_, fc_b, s == 0, C, FCN_, 0, 0, m0, n0, s * 128);
        }
        gridbar(gen);
        // D4: out partials [B,128], K=512 (S=4); A = relu(sum5 fc)
#pragma unroll 1
        for (int tl = bid; tl < 4 * 2 * 4; tl += nblk) {
            int s = tl % 4, r = tl / 4;
            int n0 = (r % 2) * 64, m0 = (r / 2) * 32;
            float* C = g_outp + (size_t)s * (B_ * D_);
            tile_gemm(&sm, g_fcp, FCN_, (size_t)B_ * FCN_, 5, 2, out_W, FCN_, out_b, s == 0,
                      C, D_, 0, 0, m0, n0, s * 128);
        }
        gridbar(gen);
    }

    // ---------- final x_mu[:, TL-1, :] ----------
    for (int i = gtid; i < B_ * D_ / 4; i += nthr) {
        int m = i / 32, d = (i % 32) * 4;
        float4 v = make_float4(0.f,0.f,0.f,0.f);
#pragma unroll
        for (int s = 0; s < 4; s++) {
            float4 u = ld4cg(&g_outp[(size_t)s * B_ * D_ + m * D_ + d]);
            v.x+=u.x; v.y+=u.y; v.z+=u.z; v.w+=u.w;
        }
        *(float4*)&x_mu[((size_t)m * TL_ + TL_ - 1) * D_ + d] = v;
    }
}

// ---------------- host launch: single graph node ---------------------------
extern "C" void kernel_launch(void* const* d_in, const int* in_sizes, int n_in,
                              void* d_out, int out_size)
{
    (void)in_sizes; (void)n_in; (void)out_size;
    const float* past    = (const float*)d_in[0];
    const float* future  = (const float*)d_in[1];
    const float* eps     = (const float*)d_in[2];
    const float* phi_Wih = (const float*)d_in[3];
    const float* phi_Whh = (const float*)d_in[4];
    const float* phi_bih = (const float*)d_in[5];
    const float* phi_bhh = (const float*)d_in[6];
    const float* xr_Wih  = (const float*)d_in[7];
    const float* xr_Whh  = (const float*)d_in[8];
    const float* xr_bih  = (const float*)d_in[9];
    const float* xr_bhh  = (const float*)d_in[10];
    const float* mu_W1   = (const float*)d_in[11];
    const float* mu_b1   = (const float*)d_in[12];
    const float* mu_W2   = (const float*)d_in[13];
    const float* mu_b2   = (const float*)d_in[14];
    const float* mu_W3   = (const float*)d_in[15];
    const float* mu_b3   = (const float*)d_in[16];
    const float* lv_W1   = (const float*)d_in[17];
    const float* lv_b1   = (const float*)d_in[18];
    const float* lv_W2   = (const float*)d_in[19];
    const float* lv_b2   = (const float*)d_in[20];
    const float* lv_W3   = (const float*)d_in[21];
    const float* lv_b3   = (const float*)d_in[22];
    const float* dec_Wih = (const float*)d_in[23];
    const float* dec_Whh = (const float*)d_in[24];
    const float* dec_bih = (const float*)d_in[25];
    const float* dec_bhh = (const float*)d_in[26];
    const float* fc_W    = (const float*)d_in[27];
    const float* fc_b    = (const float*)d_in[28];
    const float* out_W   = (const float*)d_in[29];
    const float* out_b   = (const float*)d_in[30];

    float* outp = (float*)d_out;
    float* x_mu = outp;
    float* z_mu = outp + (size_t)B_ * TL_ * D_;
    float* z_lv = z_mu + (size_t)B_ * LD_;

    int dev = 0, sms = 148;
    cudaGetDevice(&dev);
    cudaDeviceGetAttribute(&sms, cudaDevAttrMultiProcessorCount, dev);
    int nblk = sms * 2;
    if (nblk > MAXBLK) nblk = MAXBLK;

    vae_persistent<<<nblk, 256>>>(
        past, future, eps,
        phi_Wih, phi_Whh, phi_bih, phi_bhh,
        xr_Wih, xr_Whh, xr_bih, xr_bhh,
        mu_W1, mu_b1, mu_W2, mu_b2, mu_W3, mu_b3,
        lv_W1, lv_b1, lv_W2, lv_b2, lv_W3, lv_b3,
        dec_Wih, dec_Whh, dec_bih, dec_bhh,
        fc_W, fc_b, out_W, out_b,
        x_mu, z_mu, z_lv);
}